// round 3
// baseline (speedup 1.0000x reference)
#include <cuda_runtime.h>
#include <math.h>

#define DGRID 200
#define NCELL 8000000
#define AT 4            /* a-layers per block (looped per thread) */
#define BT 5            /* b rows per block */
#define CW 204          /* padded row width: c in [-2, 201] */
#define SAH (AT + 4)    /* 8 halo a-layers */
#define SBH (BT + 4)    /* 9 halo b-rows */
#define SKEYN (SAH * SBH * CW)   /* 14688 words = 58752 B */
#define NTHREADS 1000

#define KNF 600000.0f
#define KEYMASK 0xFCFCFCFCu

__device__ __forceinline__ int wrapD(int v) {
    if (v < 0) v += DGRID;
    else if (v >= DGRID) v -= DGRID;
    return v;
}

__global__ void __launch_bounds__(NTHREADS, 1)
dem_step_kernel(const float* __restrict__ xg, const float* __restrict__ yg,
                const float* __restrict__ zg, const float* __restrict__ vxg,
                const float* __restrict__ vyg, const float* __restrict__ vzg,
                const float* __restrict__ mg, float* __restrict__ out,
                float eta, float dtpm, float gpm)
{
    extern __shared__ unsigned int skey[];   // [SAH][SBH][CW]

    const int tid = threadIdx.x + 200 * threadIdx.y;
    const int b0 = blockIdx.x * BT;
    const int a0 = blockIdx.y * AT;

    // ---- build quantized key tile (periodic halo) ----
    for (int s = tid; s < SKEYN; s += NTHREADS) {
        int sc = s % CW; int r = s / CW; int sb = r % SBH; int sa = r / SBH;
        int ga = wrapD(a0 - 2 + sa);
        int gb = wrapD(b0 - 2 + sb);
        int gc = wrapD(sc - 2);
        int g = (ga * DGRID + gb) * DGRID + gc;
        unsigned kx = (unsigned)__float2int_rz(__ldg(xg + g) * 10.0f);
        unsigned ky = (unsigned)__float2int_rz(__ldg(yg + g) * 10.0f);
        unsigned kz = (unsigned)__float2int_rz(__ldg(zg + g) * 10.0f);
        skey[s] = kx | (ky << 8) | (kz << 16);
    }
    __syncthreads();

    const int c  = threadIdx.x;       // 0..199 (consecutive lanes -> consecutive c)
    const int bl = threadIdx.y;       // 0..4
    const int gb = b0 + bl;

    for (int aa = 0; aa < AT; ++aa) {
        const int ga = a0 + aa;
        const int gp = (ga * DGRID + gb) * DGRID + c;

        const float xp = __ldg(xg + gp);
        const float yp = __ldg(yg + gp);
        const float zp = __ldg(zg + gp);
        const float vx = __ldg(vxg + gp);
        const float vy = __ldg(vyg + gp);
        const float vz = __ldg(vzg + gp);
        const float m  = __ldg(mg + gp);

        unsigned ckx = (unsigned)__float2int_rz(xp * 10.0f);
        unsigned cky = (unsigned)__float2int_rz(yp * 10.0f);
        unsigned ckz = (unsigned)__float2int_rz(zp * 10.0f);
        const unsigned ck = ckx | (cky << 8) | (ckz << 16);

        float fx = 0.f, fy = 0.f, fz = 0.f;

        #pragma unroll 1
        for (int oa = 0; oa < 5; ++oa) {
            const unsigned int* pl = skey + (aa + oa) * (SBH * CW);
            #pragma unroll
            for (int ob = 0; ob < 5; ++ob) {
                const unsigned int* row = pl + (bl + ob) * CW + c;
                unsigned d0 = __vabsdiffu4(row[0], ck) & KEYMASK;
                unsigned d1 = __vabsdiffu4(row[1], ck) & KEYMASK;
                unsigned d2 = __vabsdiffu4(row[2], ck) & KEYMASK;
                unsigned d3 = __vabsdiffu4(row[3], ck) & KEYMASK;
                unsigned d4 = __vabsdiffu4(row[4], ck) & KEYMASK;
                unsigned mn = min(min(d0, d1), min(d2, min(d3, d4)));
                if (mn == 0u) {
                    // rare: at least one candidate in this 5-cell window
                    unsigned dd[5] = {d0, d1, d2, d3, d4};
                    #pragma unroll 1
                    for (int oc = 0; oc < 5; ++oc) {
                        if (dd[oc] != 0u) continue;
                        int na = wrapD(ga + oa - 2);
                        int nb = wrapD(gb + ob - 2);
                        int nc = wrapD(c + oc - 2);
                        int gq = (na * DGRID + nb) * DGRID + nc;
                        float dx = xp - __ldg(xg + gq);
                        float dy = yp - __ldg(yg + gq);
                        float dz = zp - __ldg(zg + gq);
                        float sq = fmaf(dx, dx, fmaf(dy, dy, dz * dz));
                        if (sq > 0.f) {
                            float dist = sqrtf(sq);
                            if (dist < 0.1f) {
                                float dcl = fmaxf(dist, 1e-4f);
                                float dvx = vx - __ldg(vxg + gq);
                                float dvy = vy - __ldg(vyg + gq);
                                float dvz = vz - __ldg(vzg + gq);
                                float vn = (dvx * dx + dvy * dy + dvz * dz) / dcl;
                                float coef = 2.0f * (KNF * (dist - 0.1f) + eta * vn) / dcl;
                                fx = fmaf(coef, dx, fx);
                                fy = fmaf(coef, dy, fy);
                                fz = fmaf(coef, dz, fz);
                            }
                        }
                    }
                }
            }
        }

        // ---- wall boundary forces + semi-implicit Euler update ----
        float lft = (xp > 0.1f && xp < 0.15f) ? 1.f : 0.f;
        float rgt = (xp > 9.9f) ? 1.f : 0.f;
        float rtx = ((xp - 10.0f) + 0.05f) + 0.05f;
        float fxb = KNF*lft*(0.15f - xp) - KNF*rgt*rtx - eta*vx*lft - eta*vx*rgt;

        float bot = (yp > 0.1f && yp < 0.15f) ? 1.f : 0.f;
        float top = (yp > 9.9f) ? 1.f : 0.f;
        float rty = ((yp - 10.0f) + 0.05f) + 0.05f;
        float fyb = KNF*bot*(0.15f - yp) - KNF*top*rty - eta*vy*bot - eta*vy*top;

        float fwd = (zp > 0.1f && zp < 0.15f) ? 1.f : 0.f;
        float bck = (zp > 9.9f) ? 1.f : 0.f;
        float rtz = ((zp - 10.0f) + 0.05f) + 0.05f;
        float fzb = KNF*fwd*(0.15f - zp) - KNF*bck*rtz - eta*vz*fwd - eta*vz*bck;

        float vx2 = vx + dtpm * (m * (fxb - fx));
        float vy2 = vy + dtpm * (m * (fyb - fy));
        float vz2 = vz + dtpm * (m * ((gpm - fz) + fzb));
        float x2 = xp + 1e-4f * vx2;
        float y2 = yp + 1e-4f * vy2;
        float z2 = zp + 1e-4f * vz2;

        out[(size_t)0*NCELL + gp] = x2;
        out[(size_t)1*NCELL + gp] = y2;
        out[(size_t)2*NCELL + gp] = z2;
        out[(size_t)3*NCELL + gp] = vx2;
        out[(size_t)4*NCELL + gp] = vy2;
        out[(size_t)5*NCELL + gp] = vz2;
    }
}

extern "C" void kernel_launch(void* const* d_in, const int* in_sizes, int n_in,
                              void* d_out, int out_size)
{
    const float* xg  = (const float*)d_in[0];
    const float* yg  = (const float*)d_in[1];
    const float* zg  = (const float*)d_in[2];
    const float* vxg = (const float*)d_in[3];
    const float* vyg = (const float*)d_in[4];
    const float* vzg = (const float*)d_in[5];
    const float* mg  = (const float*)d_in[6];
    float* out = (float*)d_out;

    // constants replicated from the reference (double precision, then f32)
    const double PMd   = 4.0/3.0 * 3.1415 * 0.05*0.05*0.05 * 2700.0;
    const double alpha = 0.6931471805599453 / 3.141592653589793; // -ln(0.5)/pi
    const double gamm  = alpha / sqrt(alpha*alpha + 1.0);
    const double ETAd  = 2.0 * gamm * sqrt(600000.0 * PMd);
    const float eta  = (float)ETAd;
    const float dtpm = (float)(1e-4 / PMd);
    const float gpm  = (float)(-9.8 * PMd);

    const size_t smem_bytes = (size_t)SKEYN * sizeof(unsigned int);

    (void)cudaFuncSetAttribute(dem_step_kernel,
                               cudaFuncAttributeMaxDynamicSharedMemorySize,
                               (int)smem_bytes);

    dim3 grid(DGRID / BT, DGRID / AT, 1);   // (40, 50)
    dim3 block(200, BT, 1);                 // 1000 threads
    dem_step_kernel<<<grid, block, smem_bytes>>>(xg, yg, zg, vxg, vyg, vzg, mg,
                                                 out, eta, dtpm, gpm);
}

// round 4
// speedup vs baseline: 1.2435x; 1.2435x over previous
#include <cuda_runtime.h>
#include <math.h>

#define DGRID 200
#define NCELL 8000000
#define AT 4            /* a-layers per block */
#define BT 5            /* b rows per block */
#define CW 204          /* padded row width: c in [-2, 201] */
#define SAH (AT + 4)    /* 8 halo a-layers */
#define SBH (BT + 4)    /* 9 halo b-rows */
#define SKEYN (SAH * SBH * CW)   /* 14688 words */
#define TCELLS (AT * BT * DGRID) /* 4000 cells per block */
#define NTHREADS 1000

#define KNF 600000.0f
#define KEYMASK 0xFCFCFCFCu

__device__ __forceinline__ int wrapD(int v) {
    if (v < 0) v += DGRID;
    else if (v >= DGRID) v -= DGRID;
    return v;
}

__global__ void __launch_bounds__(NTHREADS, 1)
dem_step_kernel(const float* __restrict__ xg, const float* __restrict__ yg,
                const float* __restrict__ zg, const float* __restrict__ vxg,
                const float* __restrict__ vyg, const float* __restrict__ vzg,
                const float* __restrict__ mg, float* __restrict__ out,
                float eta, float dtpm, float gpm)
{
    extern __shared__ char smraw[];
    unsigned int* skey = (unsigned int*)smraw;                 // [SAH][SBH][CW]
    float* fxs = (float*)(skey + SKEYN);                       // [TCELLS]
    float* fys = fxs + TCELLS;
    float* fzs = fys + TCELLS;
    unsigned short* lst = (unsigned short*)(fzs + TCELLS);     // [TCELLS]
    int* cnt = (int*)(lst + TCELLS);

    const int tid = threadIdx.x + 200 * threadIdx.y;
    const int b0 = blockIdx.x * BT;
    const int a0 = blockIdx.y * AT;
    const int c  = threadIdx.x;     // 0..199
    const int bl = threadIdx.y;     // 0..4
    const int gb = b0 + bl;

    if (tid == 0) *cnt = 0;
    __syncthreads();

    // ---- zero force accumulators ----
    for (int s = tid; s < TCELLS; s += NTHREADS) {
        fxs[s] = 0.f; fys[s] = 0.f; fzs[s] = 0.f;
    }

    // ---- build quantized key tile (periodic halo) ----
    for (int s = tid; s < SKEYN; s += NTHREADS) {
        int sc = s % CW; int r = s / CW; int sb = r % SBH; int sa = r / SBH;
        int ga = wrapD(a0 - 2 + sa);
        int gbh = wrapD(b0 - 2 + sb);
        int gc = wrapD(sc - 2);
        int g = (ga * DGRID + gbh) * DGRID + gc;
        unsigned kx = (unsigned)__float2int_rz(__ldg(xg + g) * 10.0f);
        unsigned ky = (unsigned)__float2int_rz(__ldg(yg + g) * 10.0f);
        unsigned kz = (unsigned)__float2int_rz(__ldg(zg + g) * 10.0f);
        skey[s] = kx | (ky << 8) | (kz << 16);
    }

    // ---- build compacted list of masked cells (warp-aggregated) ----
    {
        const unsigned amask = __activemask();
        const int lane = tid & 31;
        for (int aa = 0; aa < AT; ++aa) {
            const int gp = ((a0 + aa) * DGRID + gb) * DGRID + c;
            bool m = (__ldg(mg + gp) != 0.f);
            unsigned bal = __ballot_sync(amask, m);
            if (bal) {
                int base = 0;
                int leader = __ffs(bal) - 1;
                if (lane == leader) base = atomicAdd(cnt, __popc(bal));
                base = __shfl_sync(amask, base, leader);
                if (m) {
                    int pos = base + __popc(bal & ((1u << lane) - 1u));
                    lst[pos] = (unsigned short)(aa * 1000 + bl * 200 + c);
                }
            }
        }
    }
    __syncthreads();

    // ---- force phase: subtasks = (masked cell, oa) ----
    const int total = (*cnt) * 5;
    for (int i = tid; i < total; i += NTHREADS) {
        const int j  = i / 5;
        const int oa = i - j * 5;
        const int idx = (int)lst[j];
        const int aa = idx / 1000;
        const int rem = idx - aa * 1000;
        const int pb = rem / 200;
        const int pc = rem - pb * 200;

        const unsigned ck = skey[((aa + 2) * SBH + (pb + 2)) * CW + (pc + 2)];
        const unsigned int* pl = skey + (aa + oa) * (SBH * CW);

        float fx = 0.f, fy = 0.f, fz = 0.f;

        #pragma unroll
        for (int ob = 0; ob < 5; ++ob) {
            const unsigned int* row = pl + (pb + ob) * CW + pc;
            unsigned d0 = __vabsdiffu4(row[0], ck) & KEYMASK;
            unsigned d1 = __vabsdiffu4(row[1], ck) & KEYMASK;
            unsigned d2 = __vabsdiffu4(row[2], ck) & KEYMASK;
            unsigned d3 = __vabsdiffu4(row[3], ck) & KEYMASK;
            unsigned d4 = __vabsdiffu4(row[4], ck) & KEYMASK;
            unsigned mn = min(min(d0, d1), min(d2, min(d3, d4)));
            if (mn == 0u) {
                unsigned dd[5] = {d0, d1, d2, d3, d4};
                const int gp = ((a0 + aa) * DGRID + (b0 + pb)) * DGRID + pc;
                const float xp = __ldg(xg + gp);
                const float yp = __ldg(yg + gp);
                const float zp = __ldg(zg + gp);
                #pragma unroll 1
                for (int oc = 0; oc < 5; ++oc) {
                    if (dd[oc] != 0u) continue;
                    int na = wrapD(a0 + aa + oa - 2);
                    int nb = wrapD(b0 + pb + ob - 2);
                    int nc = wrapD(pc + oc - 2);
                    int gq = (na * DGRID + nb) * DGRID + nc;
                    float dx = xp - __ldg(xg + gq);
                    float dy = yp - __ldg(yg + gq);
                    float dz = zp - __ldg(zg + gq);
                    float sq = fmaf(dx, dx, fmaf(dy, dy, dz * dz));
                    if (sq > 0.f) {
                        float dist = sqrtf(sq);
                        if (dist < 0.1f) {
                            float dcl = fmaxf(dist, 1e-4f);
                            float dvx = __ldg(vxg + gp) - __ldg(vxg + gq);
                            float dvy = __ldg(vyg + gp) - __ldg(vyg + gq);
                            float dvz = __ldg(vzg + gp) - __ldg(vzg + gq);
                            float vn = (dvx * dx + dvy * dy + dvz * dz) / dcl;
                            float coef = 2.0f * (KNF * (dist - 0.1f) + eta * vn) / dcl;
                            fx = fmaf(coef, dx, fx);
                            fy = fmaf(coef, dy, fy);
                            fz = fmaf(coef, dz, fz);
                        }
                    }
                }
            }
        }
        if (fx != 0.f || fy != 0.f || fz != 0.f) {
            atomicAdd(&fxs[idx], fx);
            atomicAdd(&fys[idx], fy);
            atomicAdd(&fzs[idx], fz);
        }
    }
    __syncthreads();

    // ---- update + writeback (all cells) ----
    for (int aa = 0; aa < AT; ++aa) {
        const int gp = ((a0 + aa) * DGRID + gb) * DGRID + c;
        const int idx = aa * 1000 + bl * 200 + c;

        const float xp = __ldg(xg + gp);
        const float yp = __ldg(yg + gp);
        const float zp = __ldg(zg + gp);
        const float vx = __ldg(vxg + gp);
        const float vy = __ldg(vyg + gp);
        const float vz = __ldg(vzg + gp);
        const float m  = __ldg(mg + gp);
        const float fx = fxs[idx], fy = fys[idx], fz = fzs[idx];

        float lft = (xp > 0.1f && xp < 0.15f) ? 1.f : 0.f;
        float rgt = (xp > 9.9f) ? 1.f : 0.f;
        float rtx = ((xp - 10.0f) + 0.05f) + 0.05f;
        float fxb = KNF*lft*(0.15f - xp) - KNF*rgt*rtx - eta*vx*lft - eta*vx*rgt;

        float bot = (yp > 0.1f && yp < 0.15f) ? 1.f : 0.f;
        float top = (yp > 9.9f) ? 1.f : 0.f;
        float rty = ((yp - 10.0f) + 0.05f) + 0.05f;
        float fyb = KNF*bot*(0.15f - yp) - KNF*top*rty - eta*vy*bot - eta*vy*top;

        float fwd = (zp > 0.1f && zp < 0.15f) ? 1.f : 0.f;
        float bck = (zp > 9.9f) ? 1.f : 0.f;
        float rtz = ((zp - 10.0f) + 0.05f) + 0.05f;
        float fzb = KNF*fwd*(0.15f - zp) - KNF*bck*rtz - eta*vz*fwd - eta*vz*bck;

        float vx2 = vx + dtpm * (m * (fxb - fx));
        float vy2 = vy + dtpm * (m * (fyb - fy));
        float vz2 = vz + dtpm * (m * ((gpm - fz) + fzb));
        float x2 = xp + 1e-4f * vx2;
        float y2 = yp + 1e-4f * vy2;
        float z2 = zp + 1e-4f * vz2;

        out[(size_t)0*NCELL + gp] = x2;
        out[(size_t)1*NCELL + gp] = y2;
        out[(size_t)2*NCELL + gp] = z2;
        out[(size_t)3*NCELL + gp] = vx2;
        out[(size_t)4*NCELL + gp] = vy2;
        out[(size_t)5*NCELL + gp] = vz2;
    }
}

extern "C" void kernel_launch(void* const* d_in, const int* in_sizes, int n_in,
                              void* d_out, int out_size)
{
    const float* xg  = (const float*)d_in[0];
    const float* yg  = (const float*)d_in[1];
    const float* zg  = (const float*)d_in[2];
    const float* vxg = (const float*)d_in[3];
    const float* vyg = (const float*)d_in[4];
    const float* vzg = (const float*)d_in[5];
    const float* mg  = (const float*)d_in[6];
    float* out = (float*)d_out;

    const double PMd   = 4.0/3.0 * 3.1415 * 0.05*0.05*0.05 * 2700.0;
    const double alpha = 0.6931471805599453 / 3.141592653589793;
    const double gamm  = alpha / sqrt(alpha*alpha + 1.0);
    const double ETAd  = 2.0 * gamm * sqrt(600000.0 * PMd);
    const float eta  = (float)ETAd;
    const float dtpm = (float)(1e-4 / PMd);
    const float gpm  = (float)(-9.8 * PMd);

    const size_t smem_bytes =
        (size_t)SKEYN * sizeof(unsigned int) +
        (size_t)(3 * TCELLS) * sizeof(float) +
        (size_t)TCELLS * sizeof(unsigned short) +
        16;

    (void)cudaFuncSetAttribute(dem_step_kernel,
                               cudaFuncAttributeMaxDynamicSharedMemorySize,
                               (int)smem_bytes);

    dim3 grid(DGRID / BT, DGRID / AT, 1);   // (40, 50)
    dim3 block(200, BT, 1);                 // 1000 threads
    dem_step_kernel<<<grid, block, smem_bytes>>>(xg, yg, zg, vxg, vyg, vzg, mg,
                                                 out, eta, dtpm, gpm);
}